// round 2
// baseline (speedup 1.0000x reference)
#include <cuda_runtime.h>

#define BB 16384
#define DD 256
#define HH 1024
#define EE 8
#define KXT 257   // D+1
#define TOPK 2

// ---------------- scratch (static device memory; no allocations) -------------
__device__ float g_h[(size_t)BB * HH];          // router hidden       (64 MiB)
__device__ float g_h1[(size_t)2 * BB * HH];     // expert fc1 out      (128 MiB)
__device__ float g_h2[(size_t)2 * BB * HH];     // expert fc2 out      (128 MiB)
__device__ float g_eout[(size_t)2 * BB * DD];   // scaled expert out   (32 MiB)
__device__ int   g_perm[2 * BB];                // assignment -> token
__device__ float g_wgt[2 * BB];                 // assignment -> alpha
__device__ int   g_slot[2 * BB];                // (token,j) -> assignment
__device__ int   g_topk_idx[BB * TOPK];
__device__ float g_topk_a[BB * TOPK];
__device__ int   g_cnt[EE];
__device__ int   g_off[EE];
__device__ int   g_cursor[EE];

__device__ __forceinline__ float silu(float v) {
    return v / (1.f + __expf(-v));
}

// Use precise expf for router math (cheap, small count)
__device__ __forceinline__ float silu_precise(float v) {
    return v / (1.f + expf(-v));
}

// ---------------- reset ------------------------------------------------------
__global__ void reset_kernel() {
    if (threadIdx.x < EE) g_cnt[threadIdx.x] = 0;
}

// ---------------- generic tiled SGEMM ---------------------------------------
// MODE 0: router  : A = [x|t] (dense rows), W=Rw1 (257x1024), silu -> g_h
// MODE 1: fc1     : A = [x|t] gathered by g_perm, W=Ew1[e],   silu -> g_h1
// MODE 2: fc2     : A = g_h1,                       W=Ew2[e], silu -> g_h2
// MODE 3: fc3     : A = g_h2,                       W=Ew3[e], *alpha -> g_eout
template <int MODE>
__global__ __launch_bounds__(256)
void gemm_kernel(const float* __restrict__ X, const float* __restrict__ T,
                 const float* __restrict__ W, const float* __restrict__ Bias)
{
    constexpr int KK = (MODE <= 1) ? KXT : HH;
    constexpr int NN = (MODE == 3) ? DD : HH;
    constexpr int BM = 128, BN = 128, BK = 8;
    constexpr int NKT = (KK + BK - 1) / BK;

    const int e = (MODE == 0) ? 0 : blockIdx.z;
    int m_base, m_count;
    if (MODE == 0) { m_base = 0; m_count = BB; }
    else           { m_base = g_off[e]; m_count = g_cnt[e]; }

    const int row0 = blockIdx.y * BM;       // row offset within bucket
    if (row0 >= m_count) return;
    const int col0 = blockIdx.x * BN;

    const float* __restrict__ Wp = W + (MODE == 0 ? (size_t)0 : (size_t)e * KK * NN);
    const float* __restrict__ Bp = Bias + (MODE == 0 ? (size_t)0 : (size_t)e * NN);

    __shared__ __align__(16) float As[BK][BM + 4];
    __shared__ __align__(16) float Bs[BK][BN + 4];

    const int tid = threadIdx.x;
    const int tx = tid & 15;       // 0..15 -> 8 output cols each
    const int ty = tid >> 4;       // 0..15 -> 8 output rows each

    // A-tile loader: thread -> (row, 4 k's)
    const int a_row = tid >> 1;            // 0..127
    const int a_k4  = (tid & 1) * 4;       // 0 or 4
    // B-tile loader: thread -> (k, 4 n's)
    const int b_k  = tid >> 5;             // 0..7
    const int b_n  = (tid & 31) * 4;       // 0..124

    const bool a_valid = (row0 + a_row) < m_count;
    int tok = 0;
    const float* __restrict__ Arow = nullptr;
    if (MODE == 0) {
        tok = row0 + a_row;
    } else if (MODE == 1) {
        if (a_valid) tok = g_perm[m_base + row0 + a_row];
    } else {
        const float* src = (MODE == 2) ? g_h1 : g_h2;
        Arow = src + (size_t)(m_base + row0 + a_row) * KK;
    }

    float acc[8][8];
    #pragma unroll
    for (int i = 0; i < 8; i++)
        #pragma unroll
        for (int j = 0; j < 8; j++) acc[i][j] = 0.f;

    for (int kt = 0; kt < NKT; kt++) {
        const int kb = kt * BK;

        // ---- load A tile ----
        if (MODE >= 2) {
            float4 v = make_float4(0.f, 0.f, 0.f, 0.f);
            if (a_valid) v = *(const float4*)(Arow + kb + a_k4);
            As[a_k4 + 0][a_row] = v.x;
            As[a_k4 + 1][a_row] = v.y;
            As[a_k4 + 2][a_row] = v.z;
            As[a_k4 + 3][a_row] = v.w;
        } else {
            #pragma unroll
            for (int l = 0; l < 4; l++) {
                const int k = kb + a_k4 + l;
                float v = 0.f;
                if (a_valid) {
                    if (k < DD)        v = X[(size_t)tok * DD + k];
                    else if (k == DD)  v = T[tok];
                }
                As[a_k4 + l][a_row] = v;
            }
        }

        // ---- load B tile ----
        {
            const int k = kb + b_k;
            float4 v = make_float4(0.f, 0.f, 0.f, 0.f);
            if ((KK % BK == 0) || (k < KK))
                v = *(const float4*)(Wp + (size_t)k * NN + col0 + b_n);
            Bs[b_k][b_n + 0] = v.x;
            Bs[b_k][b_n + 1] = v.y;
            Bs[b_k][b_n + 2] = v.z;
            Bs[b_k][b_n + 3] = v.w;
        }

        __syncthreads();

        #pragma unroll
        for (int k = 0; k < BK; k++) {
            float a[8], b[8];
            *(float4*)(a)     = *(const float4*)&As[k][ty * 8];
            *(float4*)(a + 4) = *(const float4*)&As[k][ty * 8 + 4];
            *(float4*)(b)     = *(const float4*)&Bs[k][tx * 8];
            *(float4*)(b + 4) = *(const float4*)&Bs[k][tx * 8 + 4];
            #pragma unroll
            for (int i = 0; i < 8; i++)
                #pragma unroll
                for (int j = 0; j < 8; j++)
                    acc[i][j] = fmaf(a[i], b[j], acc[i][j]);
        }

        __syncthreads();
    }

    // ---- epilogue ----
    float bias[8];
    #pragma unroll
    for (int j = 0; j < 8; j++) bias[j] = Bp[col0 + tx * 8 + j];

    #pragma unroll
    for (int i = 0; i < 8; i++) {
        const int rloc = row0 + ty * 8 + i;
        if (rloc >= m_count) continue;
        const size_t a_idx = (size_t)(m_base + rloc);
        float* dst;
        float scale = 1.f;
        if (MODE == 0)      dst = g_h  + (size_t)rloc * HH;
        else if (MODE == 1) dst = g_h1 + a_idx * HH;
        else if (MODE == 2) dst = g_h2 + a_idx * HH;
        else              { dst = g_eout + a_idx * DD; scale = g_wgt[a_idx]; }

        float4 o[2];
        float tmp[8];
        #pragma unroll
        for (int j = 0; j < 8; j++) {
            float v = acc[i][j] + bias[j];
            if (MODE <= 2) v = silu_precise(v);
            else           v *= scale;
            tmp[j] = v;
        }
        o[0] = make_float4(tmp[0], tmp[1], tmp[2], tmp[3]);
        o[1] = make_float4(tmp[4], tmp[5], tmp[6], tmp[7]);
        *(float4*)(dst + col0 + tx * 8)     = o[0];
        *(float4*)(dst + col0 + tx * 8 + 4) = o[1];
    }
}

// ---------------- router logits + top-2 softmax ------------------------------
__global__ __launch_bounds__(256)
void logits_topk_kernel(const float* __restrict__ Rw2, const float* __restrict__ Rb2)
{
    const int warp = (blockIdx.x * (blockDim.x >> 5)) + (threadIdx.x >> 5);
    if (warp >= BB) return;
    const int b = warp;
    const int lane = threadIdx.x & 31;

    float l[EE];
    #pragma unroll
    for (int e = 0; e < EE; e++) l[e] = 0.f;

    const float* __restrict__ hrow = g_h + (size_t)b * HH;
    for (int k = lane; k < HH; k += 32) {
        const float hv = hrow[k];
        const float4 w0 = *(const float4*)(Rw2 + (size_t)k * EE);
        const float4 w1 = *(const float4*)(Rw2 + (size_t)k * EE + 4);
        l[0] = fmaf(hv, w0.x, l[0]);
        l[1] = fmaf(hv, w0.y, l[1]);
        l[2] = fmaf(hv, w0.z, l[2]);
        l[3] = fmaf(hv, w0.w, l[3]);
        l[4] = fmaf(hv, w1.x, l[4]);
        l[5] = fmaf(hv, w1.y, l[5]);
        l[6] = fmaf(hv, w1.z, l[6]);
        l[7] = fmaf(hv, w1.w, l[7]);
    }
    #pragma unroll
    for (int off = 16; off > 0; off >>= 1)
        #pragma unroll
        for (int e = 0; e < EE; e++)
            l[e] += __shfl_xor_sync(0xffffffff, l[e], off);

    if (lane == 0) {
        #pragma unroll
        for (int e = 0; e < EE; e++) l[e] += Rb2[e];
        // top-2 (first index wins on ties, matching jax top_k)
        int i0 = 0;
        #pragma unroll
        for (int e = 1; e < EE; e++) if (l[e] > l[i0]) i0 = e;
        int i1 = (i0 == 0) ? 1 : 0;
        #pragma unroll
        for (int e = 0; e < EE; e++)
            if (e != i0 && l[e] > l[i1]) i1 = e;
        const float e1 = expf(l[i1] - l[i0]);
        const float inv = 1.f / (1.f + e1);
        g_topk_idx[b * 2 + 0] = i0;
        g_topk_idx[b * 2 + 1] = i1;
        g_topk_a[b * 2 + 0] = inv;
        g_topk_a[b * 2 + 1] = e1 * inv;
        atomicAdd(&g_cnt[i0], 1);
        atomicAdd(&g_cnt[i1], 1);
    }
}

// ---------------- bucket offsets (E=8, single thread) ------------------------
__global__ void scan_kernel()
{
    if (threadIdx.x == 0) {
        int s = 0;
        for (int e = 0; e < EE; e++) {
            g_off[e] = s;
            g_cursor[e] = s;
            s += g_cnt[e];
        }
    }
}

// ---------------- scatter tokens into expert buckets -------------------------
__global__ __launch_bounds__(256)
void scatter_kernel()
{
    const int b = blockIdx.x * blockDim.x + threadIdx.x;
    if (b >= BB) return;
    #pragma unroll
    for (int j = 0; j < TOPK; j++) {
        const int e = g_topk_idx[b * 2 + j];
        const int pos = atomicAdd(&g_cursor[e], 1);
        g_perm[pos] = b;
        g_wgt[pos]  = g_topk_a[b * 2 + j];
        g_slot[b * 2 + j] = pos;
    }
}

// ---------------- deterministic 2-way combine --------------------------------
__global__ __launch_bounds__(256)
void combine_kernel(float* __restrict__ out)
{
    const int idx = blockIdx.x * blockDim.x + threadIdx.x;   // per float4
    if (idx >= BB * DD / 4) return;
    const int b = idx / (DD / 4);
    const int q = idx % (DD / 4);
    const int s0 = g_slot[b * 2 + 0];
    const int s1 = g_slot[b * 2 + 1];
    const float4 v0 = *((const float4*)g_eout + (size_t)s0 * (DD / 4) + q);
    const float4 v1 = *((const float4*)g_eout + (size_t)s1 * (DD / 4) + q);
    float4 r;
    r.x = v0.x + v1.x;
    r.y = v0.y + v1.y;
    r.z = v0.z + v1.z;
    r.w = v0.w + v1.w;
    ((float4*)out)[idx] = r;
}

// ---------------- launch -----------------------------------------------------
extern "C" void kernel_launch(void* const* d_in, const int* in_sizes, int n_in,
                              void* d_out, int out_size)
{
    const float* t   = (const float*)d_in[0];
    const float* x   = (const float*)d_in[1];
    const float* Rw1 = (const float*)d_in[2];
    const float* Rb1 = (const float*)d_in[3];
    const float* Rw2 = (const float*)d_in[4];
    const float* Rb2 = (const float*)d_in[5];
    const float* Ew1 = (const float*)d_in[6];
    const float* Eb1 = (const float*)d_in[7];
    const float* Ew2 = (const float*)d_in[8];
    const float* Eb2 = (const float*)d_in[9];
    const float* Ew3 = (const float*)d_in[10];
    const float* Eb3 = (const float*)d_in[11];
    float* out = (float*)d_out;

    reset_kernel<<<1, 32>>>();

    // router hidden: (B x 257) @ (257 x 1024) + silu
    gemm_kernel<0><<<dim3(HH / 128, BB / 128, 1), 256>>>(x, t, Rw1, Rb1);

    // logits + top-2 softmax gate
    logits_topk_kernel<<<BB / 8, 256>>>(Rw2, Rb2);
    scan_kernel<<<1, 32>>>();
    scatter_kernel<<<BB / 256, 256>>>();

    // grouped expert MLP over 2B assignments (max 128 row tiles per expert)
    gemm_kernel<1><<<dim3(HH / 128, 128, EE), 256>>>(x, t, Ew1, Eb1);
    gemm_kernel<2><<<dim3(HH / 128, 128, EE), 256>>>(nullptr, nullptr, Ew2, Eb2);
    gemm_kernel<3><<<dim3(DD / 128, 128, EE), 256>>>(nullptr, nullptr, Ew3, Eb3);

    // out[b] = alpha0*eout[slot0] + alpha1*eout[slot1]
    combine_kernel<<<(BB * DD / 4 + 255) / 256, 256>>>(out);
}

// round 3
// speedup vs baseline: 1.8593x; 1.8593x over previous
#include <cuda_runtime.h>

#define BB 16384
#define DD 256
#define HH 1024
#define EE 8
#define KXT 257   // D+1
#define TOPK 2

// ---------------- scratch (static device memory; no allocations) -------------
__device__ float g_h[(size_t)BB * HH];          // router hidden       (64 MiB)
__device__ float g_h1[(size_t)2 * BB * HH];     // expert fc1 out      (128 MiB)
__device__ float g_h2[(size_t)2 * BB * HH];     // expert fc2 out      (128 MiB)
__device__ float g_eout[(size_t)2 * BB * DD];   // scaled expert out   (32 MiB)
__device__ int   g_perm[2 * BB];                // assignment -> token
__device__ float g_wgt[2 * BB];                 // assignment -> alpha
__device__ int   g_slot[2 * BB];                // (token,j) -> assignment
__device__ int   g_topk_idx[BB * TOPK];
__device__ float g_topk_a[BB * TOPK];
__device__ int   g_cnt[EE];
__device__ int   g_off[EE];
__device__ int   g_cursor[EE];

__device__ __forceinline__ float silu_precise(float v) {
    return v / (1.f + expf(-v));
}

__device__ __forceinline__ unsigned f2tf(float v) {
    unsigned u;
    asm("cvt.rna.tf32.f32 %0, %1;" : "=r"(u) : "f"(v));
    return u;
}

__device__ __forceinline__ void mma_tf32(float* d, const unsigned* a, const unsigned* b) {
    asm volatile(
        "mma.sync.aligned.m16n8k8.row.col.f32.tf32.tf32.f32 "
        "{%0,%1,%2,%3}, {%4,%5,%6,%7}, {%8,%9}, {%0,%1,%2,%3};"
        : "+f"(d[0]), "+f"(d[1]), "+f"(d[2]), "+f"(d[3])
        : "r"(a[0]), "r"(a[1]), "r"(a[2]), "r"(a[3]), "r"(b[0]), "r"(b[1]));
}

// ---------------- reset ------------------------------------------------------
__global__ void reset_kernel() {
    if (threadIdx.x < EE) g_cnt[threadIdx.x] = 0;
}

// ---------------- fp32 router GEMM (exact; gating must match reference) ------
__global__ __launch_bounds__(256)
void router_gemm_kernel(const float* __restrict__ X, const float* __restrict__ T,
                        const float* __restrict__ W, const float* __restrict__ Bias)
{
    constexpr int KK = KXT, NN = HH;
    constexpr int BM = 128, BN = 128, BK = 8;
    constexpr int NKT = (KK + BK - 1) / BK;

    const int row0 = blockIdx.y * BM;
    const int col0 = blockIdx.x * BN;

    __shared__ __align__(16) float As[BK][BM + 4];
    __shared__ __align__(16) float Bs[BK][BN + 4];

    const int tid = threadIdx.x;
    const int tx = tid & 15;
    const int ty = tid >> 4;
    const int a_row = tid >> 1;
    const int a_k4  = (tid & 1) * 4;
    const int b_k  = tid >> 5;
    const int b_n  = (tid & 31) * 4;

    const int tok = row0 + a_row;

    float acc[8][8];
    #pragma unroll
    for (int i = 0; i < 8; i++)
        #pragma unroll
        for (int j = 0; j < 8; j++) acc[i][j] = 0.f;

    for (int kt = 0; kt < NKT; kt++) {
        const int kb = kt * BK;
        #pragma unroll
        for (int l = 0; l < 4; l++) {
            const int k = kb + a_k4 + l;
            float v = 0.f;
            if (k < DD)       v = X[(size_t)tok * DD + k];
            else if (k == DD) v = T[tok];
            As[a_k4 + l][a_row] = v;
        }
        {
            const int k = kb + b_k;
            float4 v = make_float4(0.f, 0.f, 0.f, 0.f);
            if (k < KK) v = *(const float4*)(W + (size_t)k * NN + col0 + b_n);
            Bs[b_k][b_n + 0] = v.x;
            Bs[b_k][b_n + 1] = v.y;
            Bs[b_k][b_n + 2] = v.z;
            Bs[b_k][b_n + 3] = v.w;
        }
        __syncthreads();
        #pragma unroll
        for (int k = 0; k < BK; k++) {
            float a[8], b[8];
            *(float4*)(a)     = *(const float4*)&As[k][ty * 8];
            *(float4*)(a + 4) = *(const float4*)&As[k][ty * 8 + 4];
            *(float4*)(b)     = *(const float4*)&Bs[k][tx * 8];
            *(float4*)(b + 4) = *(const float4*)&Bs[k][tx * 8 + 4];
            #pragma unroll
            for (int i = 0; i < 8; i++)
                #pragma unroll
                for (int j = 0; j < 8; j++)
                    acc[i][j] = fmaf(a[i], b[j], acc[i][j]);
        }
        __syncthreads();
    }

    float bias[8];
    #pragma unroll
    for (int j = 0; j < 8; j++) bias[j] = Bias[col0 + tx * 8 + j];

    #pragma unroll
    for (int i = 0; i < 8; i++) {
        const int rloc = row0 + ty * 8 + i;
        float* dst = g_h + (size_t)rloc * HH;
        float tmp[8];
        #pragma unroll
        for (int j = 0; j < 8; j++)
            tmp[j] = silu_precise(acc[i][j] + bias[j]);
        *(float4*)(dst + col0 + tx * 8)     = make_float4(tmp[0], tmp[1], tmp[2], tmp[3]);
        *(float4*)(dst + col0 + tx * 8 + 4) = make_float4(tmp[4], tmp[5], tmp[6], tmp[7]);
    }
}

// ---------------- TF32 tensor-core grouped GEMM ------------------------------
// MODE 1: fc1 : A = [x|t] gathered by g_perm (K=257),  W=Ew1[e], silu  -> g_h1
// MODE 2: fc2 : A = g_h1 (K=1024),                     W=Ew2[e], silu  -> g_h2
// MODE 3: fc3 : A = g_h2 (K=1024),                     W=Ew3[e], *alpha-> g_eout
template <int MODE>
__global__ __launch_bounds__(256, 2)
void tgemm_kernel(const float* __restrict__ X, const float* __restrict__ T,
                  const float* __restrict__ W, const float* __restrict__ Bias)
{
    constexpr int KK = (MODE == 1) ? KXT : HH;
    constexpr int NN = (MODE == 3) ? DD : HH;
    constexpr int BM = 128, BN = 128, BK = 16;
    constexpr int NKT = (KK + BK - 1) / BK;

    const int e = blockIdx.z;
    const int m_base  = g_off[e];
    const int m_count = g_cnt[e];
    const int row0 = blockIdx.y * BM;
    if (row0 >= m_count) return;
    const int col0 = blockIdx.x * BN;

    const float* __restrict__ Wp = W + (size_t)e * KK * NN;
    const float* __restrict__ Bp = Bias + (size_t)e * NN;

    __shared__ __align__(16) unsigned As[BK][BM + 4];   // tf32 bits, [k][m]
    __shared__ __align__(16) unsigned Bs[BK][BN + 4];   // tf32 bits, [k][n]

    const int tid  = threadIdx.x;
    const int warp = tid >> 5;
    const int lane = tid & 31;
    const int wm = warp >> 2;       // 0..1 : 64-row slab
    const int wn = warp & 3;        // 0..3 : 32-col slab
    const int r  = lane >> 2;       // 0..7
    const int c  = lane & 3;        // 0..3

    // A loader: thread -> (row a_m, 8 consecutive k's)
    const int a_m  = tid >> 1;            // 0..127
    const int a_k8 = (tid & 1) * 8;       // 0 or 8
    const bool a_valid = (row0 + a_m) < m_count;
    int tok = 0;
    const float* __restrict__ Arow = nullptr;
    if (MODE == 1) {
        if (a_valid) tok = g_perm[m_base + row0 + a_m];
    } else {
        const float* src = (MODE == 2) ? g_h1 : g_h2;
        Arow = src + (size_t)(m_base + row0 + a_m) * KK;
    }

    // B loader: thread -> (k b_k, 8 consecutive n's)
    const int b_k = tid >> 4;             // 0..15
    const int b_n = (tid & 15) * 8;       // 0..120

    float acc[4][4][4];
    #pragma unroll
    for (int mi = 0; mi < 4; mi++)
        #pragma unroll
        for (int ni = 0; ni < 4; ni++)
            #pragma unroll
            for (int q = 0; q < 4; q++) acc[mi][ni][q] = 0.f;

    for (int kt = 0; kt < NKT; kt++) {
        const int kb = kt * BK;

        // ---- A tile ----
        if (MODE == 1) {
            if (kb + a_k8 + 7 < DD) {
                float4 v0 = make_float4(0.f,0.f,0.f,0.f), v1 = v0;
                if (a_valid) {
                    v0 = *(const float4*)(X + (size_t)tok * DD + kb + a_k8);
                    v1 = *(const float4*)(X + (size_t)tok * DD + kb + a_k8 + 4);
                }
                As[a_k8 + 0][a_m] = f2tf(v0.x); As[a_k8 + 1][a_m] = f2tf(v0.y);
                As[a_k8 + 2][a_m] = f2tf(v0.z); As[a_k8 + 3][a_m] = f2tf(v0.w);
                As[a_k8 + 4][a_m] = f2tf(v1.x); As[a_k8 + 5][a_m] = f2tf(v1.y);
                As[a_k8 + 6][a_m] = f2tf(v1.z); As[a_k8 + 7][a_m] = f2tf(v1.w);
            } else {
                #pragma unroll
                for (int l = 0; l < 8; l++) {
                    const int k = kb + a_k8 + l;
                    float v = 0.f;
                    if (a_valid) {
                        if (k < DD)       v = X[(size_t)tok * DD + k];
                        else if (k == DD) v = T[tok];
                    }
                    As[a_k8 + l][a_m] = f2tf(v);
                }
            }
        } else {
            float4 v0 = make_float4(0.f,0.f,0.f,0.f), v1 = v0;
            if (a_valid) {
                v0 = *(const float4*)(Arow + kb + a_k8);
                v1 = *(const float4*)(Arow + kb + a_k8 + 4);
            }
            As[a_k8 + 0][a_m] = f2tf(v0.x); As[a_k8 + 1][a_m] = f2tf(v0.y);
            As[a_k8 + 2][a_m] = f2tf(v0.z); As[a_k8 + 3][a_m] = f2tf(v0.w);
            As[a_k8 + 4][a_m] = f2tf(v1.x); As[a_k8 + 5][a_m] = f2tf(v1.y);
            As[a_k8 + 6][a_m] = f2tf(v1.z); As[a_k8 + 7][a_m] = f2tf(v1.w);
        }

        // ---- B tile ----
        {
            const int k = kb + b_k;
            float4 v0 = make_float4(0.f,0.f,0.f,0.f), v1 = v0;
            if ((KK % BK == 0) || (k < KK)) {
                v0 = *(const float4*)(Wp + (size_t)k * NN + col0 + b_n);
                v1 = *(const float4*)(Wp + (size_t)k * NN + col0 + b_n + 4);
            }
            Bs[b_k][b_n + 0] = f2tf(v0.x); Bs[b_k][b_n + 1] = f2tf(v0.y);
            Bs[b_k][b_n + 2] = f2tf(v0.z); Bs[b_k][b_n + 3] = f2tf(v0.w);
            Bs[b_k][b_n + 4] = f2tf(v1.x); Bs[b_k][b_n + 5] = f2tf(v1.y);
            Bs[b_k][b_n + 6] = f2tf(v1.z); Bs[b_k][b_n + 7] = f2tf(v1.w);
        }

        __syncthreads();

        #pragma unroll
        for (int kk = 0; kk < BK; kk += 8) {
            unsigned af[4][4], bf[4][2];
            #pragma unroll
            for (int mi = 0; mi < 4; mi++) {
                const int mbase = wm * 64 + mi * 16;
                af[mi][0] = As[kk + c][mbase + r];
                af[mi][1] = As[kk + c][mbase + r + 8];
                af[mi][2] = As[kk + c + 4][mbase + r];
                af[mi][3] = As[kk + c + 4][mbase + r + 8];
            }
            #pragma unroll
            for (int ni = 0; ni < 4; ni++) {
                const int nbase = wn * 32 + ni * 8;
                bf[ni][0] = Bs[kk + c][nbase + r];
                bf[ni][1] = Bs[kk + c + 4][nbase + r];
            }
            #pragma unroll
            for (int mi = 0; mi < 4; mi++)
                #pragma unroll
                for (int ni = 0; ni < 4; ni++)
                    mma_tf32(acc[mi][ni], af[mi], bf[ni]);
        }

        __syncthreads();
    }

    // ---- epilogue ----
    // D frag: q0:(r, 2c), q1:(r, 2c+1), q2:(r+8, 2c), q3:(r+8, 2c+1)
    float bias2[4][2];
    #pragma unroll
    for (int ni = 0; ni < 4; ni++) {
        const int col = col0 + wn * 32 + ni * 8 + c * 2;
        bias2[ni][0] = Bp[col];
        bias2[ni][1] = Bp[col + 1];
    }

    #pragma unroll
    for (int mi = 0; mi < 4; mi++) {
        #pragma unroll
        for (int h = 0; h < 2; h++) {
            const int rloc = row0 + wm * 64 + mi * 16 + r + h * 8;
            if (rloc >= m_count) continue;
            const size_t a_idx = (size_t)(m_base + rloc);
            float* dst;
            float scale = 1.f;
            if (MODE == 1)      dst = g_h1 + a_idx * HH;
            else if (MODE == 2) dst = g_h2 + a_idx * HH;
            else              { dst = g_eout + a_idx * DD; scale = g_wgt[a_idx]; }
            #pragma unroll
            for (int ni = 0; ni < 4; ni++) {
                float v0 = acc[mi][ni][h * 2 + 0] + bias2[ni][0];
                float v1 = acc[mi][ni][h * 2 + 1] + bias2[ni][1];
                if (MODE <= 2) { v0 = silu_precise(v0); v1 = silu_precise(v1); }
                else           { v0 *= scale; v1 *= scale; }
                const int col = col0 + wn * 32 + ni * 8 + c * 2;
                *(float2*)(dst + col) = make_float2(v0, v1);
            }
        }
    }
}

// ---------------- router logits + top-2 softmax ------------------------------
__global__ __launch_bounds__(256)
void logits_topk_kernel(const float* __restrict__ Rw2, const float* __restrict__ Rb2)
{
    const int warp = (blockIdx.x * (blockDim.x >> 5)) + (threadIdx.x >> 5);
    if (warp >= BB) return;
    const int b = warp;
    const int lane = threadIdx.x & 31;

    float l[EE];
    #pragma unroll
    for (int e = 0; e < EE; e++) l[e] = 0.f;

    const float* __restrict__ hrow = g_h + (size_t)b * HH;
    for (int k = lane; k < HH; k += 32) {
        const float hv = hrow[k];
        const float4 w0 = *(const float4*)(Rw2 + (size_t)k * EE);
        const float4 w1 = *(const float4*)(Rw2 + (size_t)k * EE + 4);
        l[0] = fmaf(hv, w0.x, l[0]);
        l[1] = fmaf(hv, w0.y, l[1]);
        l[2] = fmaf(hv, w0.z, l[2]);
        l[3] = fmaf(hv, w0.w, l[3]);
        l[4] = fmaf(hv, w1.x, l[4]);
        l[5] = fmaf(hv, w1.y, l[5]);
        l[6] = fmaf(hv, w1.z, l[6]);
        l[7] = fmaf(hv, w1.w, l[7]);
    }
    #pragma unroll
    for (int off = 16; off > 0; off >>= 1)
        #pragma unroll
        for (int e = 0; e < EE; e++)
            l[e] += __shfl_xor_sync(0xffffffff, l[e], off);

    if (lane == 0) {
        #pragma unroll
        for (int e = 0; e < EE; e++) l[e] += Rb2[e];
        int i0 = 0;
        #pragma unroll
        for (int e = 1; e < EE; e++) if (l[e] > l[i0]) i0 = e;
        int i1 = (i0 == 0) ? 1 : 0;
        #pragma unroll
        for (int e = 0; e < EE; e++)
            if (e != i0 && l[e] > l[i1]) i1 = e;
        const float e1 = expf(l[i1] - l[i0]);
        const float inv = 1.f / (1.f + e1);
        g_topk_idx[b * 2 + 0] = i0;
        g_topk_idx[b * 2 + 1] = i1;
        g_topk_a[b * 2 + 0] = inv;
        g_topk_a[b * 2 + 1] = e1 * inv;
        atomicAdd(&g_cnt[i0], 1);
        atomicAdd(&g_cnt[i1], 1);
    }
}

// ---------------- bucket offsets ---------------------------------------------
__global__ void scan_kernel()
{
    if (threadIdx.x == 0) {
        int s = 0;
        for (int e = 0; e < EE; e++) {
            g_off[e] = s;
            g_cursor[e] = s;
            s += g_cnt[e];
        }
    }
}

// ---------------- scatter tokens into expert buckets -------------------------
__global__ __launch_bounds__(256)
void scatter_kernel()
{
    const int b = blockIdx.x * blockDim.x + threadIdx.x;
    if (b >= BB) return;
    #pragma unroll
    for (int j = 0; j < TOPK; j++) {
        const int e = g_topk_idx[b * 2 + j];
        const int pos = atomicAdd(&g_cursor[e], 1);
        g_perm[pos] = b;
        g_wgt[pos]  = g_topk_a[b * 2 + j];
        g_slot[b * 2 + j] = pos;
    }
}

// ---------------- deterministic 2-way combine --------------------------------
__global__ __launch_bounds__(256)
void combine_kernel(float* __restrict__ out)
{
    const int idx = blockIdx.x * blockDim.x + threadIdx.x;
    if (idx >= BB * DD / 4) return;
    const int b = idx / (DD / 4);
    const int q = idx % (DD / 4);
    const int s0 = g_slot[b * 2 + 0];
    const int s1 = g_slot[b * 2 + 1];
    const float4 v0 = *((const float4*)g_eout + (size_t)s0 * (DD / 4) + q);
    const float4 v1 = *((const float4*)g_eout + (size_t)s1 * (DD / 4) + q);
    ((float4*)out)[idx] = make_float4(v0.x + v1.x, v0.y + v1.y, v0.z + v1.z, v0.w + v1.w);
}

// ---------------- launch -----------------------------------------------------
extern "C" void kernel_launch(void* const* d_in, const int* in_sizes, int n_in,
                              void* d_out, int out_size)
{
    const float* t   = (const float*)d_in[0];
    const float* x   = (const float*)d_in[1];
    const float* Rw1 = (const float*)d_in[2];
    const float* Rb1 = (const float*)d_in[3];
    const float* Rw2 = (const float*)d_in[4];
    const float* Rb2 = (const float*)d_in[5];
    const float* Ew1 = (const float*)d_in[6];
    const float* Eb1 = (const float*)d_in[7];
    const float* Ew2 = (const float*)d_in[8];
    const float* Eb2 = (const float*)d_in[9];
    const float* Ew3 = (const float*)d_in[10];
    const float* Eb3 = (const float*)d_in[11];
    float* out = (float*)d_out;

    reset_kernel<<<1, 32>>>();

    // router hidden: exact fp32 (gating selection must match reference)
    router_gemm_kernel<<<dim3(HH / 128, BB / 128, 1), 256>>>(x, t, Rw1, Rb1);

    // logits + top-2 softmax gate (exact fp32)
    logits_topk_kernel<<<BB / 8, 256>>>(Rw2, Rb2);
    scan_kernel<<<1, 32>>>();
    scatter_kernel<<<BB / 256, 256>>>();

    // grouped expert MLP on tensor cores (TF32)
    tgemm_kernel<1><<<dim3(HH / 128, 128, EE), 256>>>(x, t, Ew1, Eb1);
    tgemm_kernel<2><<<dim3(HH / 128, 128, EE), 256>>>(nullptr, nullptr, Ew2, Eb2);
    tgemm_kernel<3><<<dim3(DD / 128, 128, EE), 256>>>(nullptr, nullptr, Ew3, Eb3);

    // out[b] = alpha0*eout[slot0] + alpha1*eout[slot1]
    combine_kernel<<<(BB * DD / 4 + 255) / 256, 256>>>(out);
}

// round 4
// speedup vs baseline: 2.1153x; 1.1377x over previous
#include <cuda_runtime.h>
#include <cuda_fp16.h>

#define BB 16384
#define DD 256
#define HH 1024
#define EE 8
#define KXT 257   // D+1
#define TOPK 2

// ---------------- scratch (static device memory; no allocations) -------------
__device__ float  g_h[(size_t)BB * HH];          // router hidden (fp32, exact)
__device__ __half g_h1[(size_t)2 * BB * HH];     // expert fc1 out (half)
__device__ __half g_h2[(size_t)2 * BB * HH];     // expert fc2 out (half)
__device__ float  g_eout[(size_t)2 * BB * DD];   // scaled expert out (fp32)
__device__ int    g_perm[2 * BB];
__device__ float  g_wgt[2 * BB];
__device__ int    g_slot[2 * BB];
__device__ int    g_topk_idx[BB * TOPK];
__device__ float  g_topk_a[BB * TOPK];
__device__ int    g_cnt[EE];
__device__ int    g_off[EE];
__device__ int    g_cursor[EE];

__device__ __forceinline__ float silu_precise(float v) {
    return v / (1.f + expf(-v));
}

__device__ __forceinline__ void mma_f16(float* d, const unsigned* a, const unsigned* b) {
    asm volatile(
        "mma.sync.aligned.m16n8k16.row.col.f32.f16.f16.f32 "
        "{%0,%1,%2,%3}, {%4,%5,%6,%7}, {%8,%9}, {%0,%1,%2,%3};"
        : "+f"(d[0]), "+f"(d[1]), "+f"(d[2]), "+f"(d[3])
        : "r"(a[0]), "r"(a[1]), "r"(a[2]), "r"(a[3]), "r"(b[0]), "r"(b[1]));
}

// ---------------- reset ------------------------------------------------------
__global__ void reset_kernel() {
    if (threadIdx.x < EE) g_cnt[threadIdx.x] = 0;
}

// ---------------- fp32 router GEMM (exact; gating must match reference) ------
__global__ __launch_bounds__(256)
void router_gemm_kernel(const float* __restrict__ X, const float* __restrict__ T,
                        const float* __restrict__ W, const float* __restrict__ Bias)
{
    constexpr int KK = KXT, NN = HH;
    constexpr int BM = 128, BN = 128, BK = 8;
    constexpr int NKT = (KK + BK - 1) / BK;

    const int row0 = blockIdx.y * BM;
    const int col0 = blockIdx.x * BN;

    __shared__ __align__(16) float As[BK][BM + 4];
    __shared__ __align__(16) float Bs[BK][BN + 4];

    const int tid = threadIdx.x;
    const int tx = tid & 15;
    const int ty = tid >> 4;
    const int a_row = tid >> 1;
    const int a_k4  = (tid & 1) * 4;
    const int b_k  = tid >> 5;
    const int b_n  = (tid & 31) * 4;

    const int tok = row0 + a_row;

    float acc[8][8];
    #pragma unroll
    for (int i = 0; i < 8; i++)
        #pragma unroll
        for (int j = 0; j < 8; j++) acc[i][j] = 0.f;

    for (int kt = 0; kt < NKT; kt++) {
        const int kb = kt * BK;
        #pragma unroll
        for (int l = 0; l < 4; l++) {
            const int k = kb + a_k4 + l;
            float v = 0.f;
            if (k < DD)       v = X[(size_t)tok * DD + k];
            else if (k == DD) v = T[tok];
            As[a_k4 + l][a_row] = v;
        }
        {
            const int k = kb + b_k;
            float4 v = make_float4(0.f, 0.f, 0.f, 0.f);
            if (k < KK) v = *(const float4*)(W + (size_t)k * NN + col0 + b_n);
            Bs[b_k][b_n + 0] = v.x;
            Bs[b_k][b_n + 1] = v.y;
            Bs[b_k][b_n + 2] = v.z;
            Bs[b_k][b_n + 3] = v.w;
        }
        __syncthreads();
        #pragma unroll
        for (int k = 0; k < BK; k++) {
            float a[8], b[8];
            *(float4*)(a)     = *(const float4*)&As[k][ty * 8];
            *(float4*)(a + 4) = *(const float4*)&As[k][ty * 8 + 4];
            *(float4*)(b)     = *(const float4*)&Bs[k][tx * 8];
            *(float4*)(b + 4) = *(const float4*)&Bs[k][tx * 8 + 4];
            #pragma unroll
            for (int i = 0; i < 8; i++)
                #pragma unroll
                for (int j = 0; j < 8; j++)
                    acc[i][j] = fmaf(a[i], b[j], acc[i][j]);
        }
        __syncthreads();
    }

    float bias[8];
    #pragma unroll
    for (int j = 0; j < 8; j++) bias[j] = Bias[col0 + tx * 8 + j];

    #pragma unroll
    for (int i = 0; i < 8; i++) {
        const int rloc = row0 + ty * 8 + i;
        float* dst = g_h + (size_t)rloc * HH;
        float tmp[8];
        #pragma unroll
        for (int j = 0; j < 8; j++)
            tmp[j] = silu_precise(acc[i][j] + bias[j]);
        *(float4*)(dst + col0 + tx * 8)     = make_float4(tmp[0], tmp[1], tmp[2], tmp[3]);
        *(float4*)(dst + col0 + tx * 8 + 4) = make_float4(tmp[4], tmp[5], tmp[6], tmp[7]);
    }
}

// ---------------- FP16 tensor-core grouped GEMM (double-buffered) ------------
// MODE 1: fc1 : A = [x|t] gathered by g_perm (K=257),  W=Ew1[e], silu  -> g_h1 (half)
// MODE 2: fc2 : A = g_h1 (K=1024),                     W=Ew2[e], silu  -> g_h2 (half)
// MODE 3: fc3 : A = g_h2 (K=1024),                     W=Ew3[e], *alpha-> g_eout (fp32)
template <int MODE>
__global__ __launch_bounds__(256)
void hgemm_kernel(const float* __restrict__ X, const float* __restrict__ T,
                  const float* __restrict__ W, const float* __restrict__ Bias)
{
    constexpr int KK = (MODE == 1) ? KXT : HH;
    constexpr int NN = (MODE == 3) ? DD : HH;
    constexpr int BM = 128, BN = 128, BK = 32;
    constexpr int RS = BK + 8;                 // 40 halves: conflict-free stride
    constexpr int NKT = (KK + BK - 1) / BK;

    const int e = blockIdx.z;
    const int m_base  = g_off[e];
    const int m_count = g_cnt[e];
    const int row0 = blockIdx.y * BM;
    if (row0 >= m_count) return;
    const int col0 = blockIdx.x * BN;

    const float* __restrict__ Wp = W + (size_t)e * KK * NN;
    const float* __restrict__ Bp = Bias + (size_t)e * NN;

    __shared__ __align__(16) __half As[2][BM * RS];
    __shared__ __align__(16) __half Bs[2][BN * RS];

    const int tid  = threadIdx.x;
    const int warp = tid >> 5;
    const int lane = tid & 31;
    const int wm = warp >> 2;       // 0..1 : 64-row slab
    const int wn = warp & 3;        // 0..3 : 32-col slab
    const int r  = lane >> 2;       // 0..7
    const int c  = lane & 3;        // 0..3

    // A loader: thread -> (row a_m, 16 consecutive k halves)
    const int a_m = tid >> 1;              // 0..127
    const int a_k = (tid & 1) * 16;        // 0 or 16
    const bool a_valid = (row0 + a_m) < m_count;
    int tok = 0;
    const __half* __restrict__ Arow = nullptr;
    if (MODE == 1) {
        if (a_valid) tok = g_perm[m_base + row0 + a_m];
    } else {
        const __half* src = (MODE == 2) ? g_h1 : g_h2;
        Arow = src + (size_t)(m_base + row0 + a_m) * KK;
    }

    // B loader: thread -> (k = b_kk, 16 consecutive n)
    const int b_kk = tid >> 3;             // 0..31
    const int b_n0 = (tid & 7) * 16;       // 0..112

    float acc[4][4][4];
    #pragma unroll
    for (int mi = 0; mi < 4; mi++)
        #pragma unroll
        for (int ni = 0; ni < 4; ni++)
            #pragma unroll
            for (int q = 0; q < 4; q++) acc[mi][ni][q] = 0.f;

    // prefetch registers
    float4 fa[4];      // MODE 1 A
    uint4  ha[2];      // MODE 2/3 A (already half)
    float4 fb[4];      // B

    auto load_a = [&](int kt) {
        const int kb = kt * BK;
        if (MODE == 1) {
            if (a_valid && (kb + a_k + 15) < DD) {
                const float* p = X + (size_t)tok * DD + kb + a_k;
                fa[0] = *(const float4*)(p);
                fa[1] = *(const float4*)(p + 4);
                fa[2] = *(const float4*)(p + 8);
                fa[3] = *(const float4*)(p + 12);
            } else {
                float tv[16];
                #pragma unroll
                for (int l = 0; l < 16; l++) {
                    const int k = kb + a_k + l;
                    float v = 0.f;
                    if (a_valid) {
                        if (k < DD)       v = X[(size_t)tok * DD + k];
                        else if (k == DD) v = T[tok];
                    }
                    tv[l] = v;
                }
                fa[0] = make_float4(tv[0], tv[1], tv[2], tv[3]);
                fa[1] = make_float4(tv[4], tv[5], tv[6], tv[7]);
                fa[2] = make_float4(tv[8], tv[9], tv[10], tv[11]);
                fa[3] = make_float4(tv[12], tv[13], tv[14], tv[15]);
            }
        } else {
            if (a_valid) {
                ha[0] = *(const uint4*)(Arow + kb + a_k);
                ha[1] = *(const uint4*)(Arow + kb + a_k + 8);
            } else {
                ha[0] = make_uint4(0, 0, 0, 0);
                ha[1] = make_uint4(0, 0, 0, 0);
            }
        }
    };

    auto store_a = [&](int buf) {
        __half* dst = &As[buf][a_m * RS + a_k];
        if (MODE == 1) {
            __half2 h[8];
            h[0] = __floats2half2_rn(fa[0].x, fa[0].y);
            h[1] = __floats2half2_rn(fa[0].z, fa[0].w);
            h[2] = __floats2half2_rn(fa[1].x, fa[1].y);
            h[3] = __floats2half2_rn(fa[1].z, fa[1].w);
            h[4] = __floats2half2_rn(fa[2].x, fa[2].y);
            h[5] = __floats2half2_rn(fa[2].z, fa[2].w);
            h[6] = __floats2half2_rn(fa[3].x, fa[3].y);
            h[7] = __floats2half2_rn(fa[3].z, fa[3].w);
            *(uint4*)(dst)     = *(uint4*)&h[0];
            *(uint4*)(dst + 8) = *(uint4*)&h[4];
        } else {
            *(uint4*)(dst)     = ha[0];
            *(uint4*)(dst + 8) = ha[1];
        }
    };

    auto load_b = [&](int kt) {
        const int kb = kt * BK;
        const int k = kb + b_kk;
        if ((KK % BK == 0) || (k < KK)) {
            const float* p = Wp + (size_t)k * NN + col0 + b_n0;
            fb[0] = *(const float4*)(p);
            fb[1] = *(const float4*)(p + 4);
            fb[2] = *(const float4*)(p + 8);
            fb[3] = *(const float4*)(p + 12);
        } else {
            fb[0] = fb[1] = fb[2] = fb[3] = make_float4(0.f, 0.f, 0.f, 0.f);
        }
    };

    auto store_b = [&](int buf) {
        __half hb[16];
        hb[0]  = __float2half_rn(fb[0].x); hb[1]  = __float2half_rn(fb[0].y);
        hb[2]  = __float2half_rn(fb[0].z); hb[3]  = __float2half_rn(fb[0].w);
        hb[4]  = __float2half_rn(fb[1].x); hb[5]  = __float2half_rn(fb[1].y);
        hb[6]  = __float2half_rn(fb[1].z); hb[7]  = __float2half_rn(fb[1].w);
        hb[8]  = __float2half_rn(fb[2].x); hb[9]  = __float2half_rn(fb[2].y);
        hb[10] = __float2half_rn(fb[2].z); hb[11] = __float2half_rn(fb[2].w);
        hb[12] = __float2half_rn(fb[3].x); hb[13] = __float2half_rn(fb[3].y);
        hb[14] = __float2half_rn(fb[3].z); hb[15] = __float2half_rn(fb[3].w);
        #pragma unroll
        for (int j = 0; j < 16; j++)
            Bs[buf][(b_n0 + j) * RS + b_kk] = hb[j];
    };

    auto compute = [&](int buf) {
        const __half* Ab = As[buf];
        const __half* Bb = Bs[buf];
        #pragma unroll
        for (int kk = 0; kk < BK; kk += 16) {
            unsigned af[4][4], bf[4][2];
            #pragma unroll
            for (int mi = 0; mi < 4; mi++) {
                const int base = (wm * 64 + mi * 16 + r) * RS + kk + 2 * c;
                af[mi][0] = *(const unsigned*)(Ab + base);
                af[mi][1] = *(const unsigned*)(Ab + base + 8 * RS);
                af[mi][2] = *(const unsigned*)(Ab + base + 8);
                af[mi][3] = *(const unsigned*)(Ab + base + 8 * RS + 8);
            }
            #pragma unroll
            for (int ni = 0; ni < 4; ni++) {
                const int base = (wn * 32 + ni * 8 + r) * RS + kk + 2 * c;
                bf[ni][0] = *(const unsigned*)(Bb + base);
                bf[ni][1] = *(const unsigned*)(Bb + base + 8);
            }
            #pragma unroll
            for (int mi = 0; mi < 4; mi++)
                #pragma unroll
                for (int ni = 0; ni < 4; ni++)
                    mma_f16(acc[mi][ni], af[mi], bf[ni]);
        }
    };

    // ---- double-buffered mainloop ----
    load_a(0); load_b(0);
    store_a(0); store_b(0);
    __syncthreads();

    for (int kt = 0; kt < NKT; kt++) {
        const int cur = kt & 1;
        if (kt + 1 < NKT) { load_a(kt + 1); load_b(kt + 1); }
        compute(cur);
        if (kt + 1 < NKT) { store_a(cur ^ 1); store_b(cur ^ 1); }
        __syncthreads();
    }

    // ---- epilogue ----
    // D frag: q0:(r, 2c), q1:(r, 2c+1), q2:(r+8, 2c), q3:(r+8, 2c+1)
    float bias2[4][2];
    #pragma unroll
    for (int ni = 0; ni < 4; ni++) {
        const int col = col0 + wn * 32 + ni * 8 + c * 2;
        bias2[ni][0] = Bp[col];
        bias2[ni][1] = Bp[col + 1];
    }

    #pragma unroll
    for (int mi = 0; mi < 4; mi++) {
        #pragma unroll
        for (int h = 0; h < 2; h++) {
            const int rloc = row0 + wm * 64 + mi * 16 + r + h * 8;
            if (rloc >= m_count) continue;
            const size_t a_idx = (size_t)(m_base + rloc);
            if (MODE == 3) {
                float* dst = g_eout + a_idx * DD;
                const float scale = g_wgt[a_idx];
                #pragma unroll
                for (int ni = 0; ni < 4; ni++) {
                    const int col = col0 + wn * 32 + ni * 8 + c * 2;
                    const float v0 = (acc[mi][ni][h * 2 + 0] + bias2[ni][0]) * scale;
                    const float v1 = (acc[mi][ni][h * 2 + 1] + bias2[ni][1]) * scale;
                    *(float2*)(dst + col) = make_float2(v0, v1);
                }
            } else {
                __half* dst = ((MODE == 1) ? g_h1 : g_h2) + a_idx * HH;
                #pragma unroll
                for (int ni = 0; ni < 4; ni++) {
                    const int col = col0 + wn * 32 + ni * 8 + c * 2;
                    const float v0 = silu_precise(acc[mi][ni][h * 2 + 0] + bias2[ni][0]);
                    const float v1 = silu_precise(acc[mi][ni][h * 2 + 1] + bias2[ni][1]);
                    *(__half2*)(dst + col) = __floats2half2_rn(v0, v1);
                }
            }
        }
    }
}

// ---------------- router logits + top-2 softmax ------------------------------
__global__ __launch_bounds__(256)
void logits_topk_kernel(const float* __restrict__ Rw2, const float* __restrict__ Rb2)
{
    const int warp = (blockIdx.x * (blockDim.x >> 5)) + (threadIdx.x >> 5);
    if (warp >= BB) return;
    const int b = warp;
    const int lane = threadIdx.x & 31;

    float l[EE];
    #pragma unroll
    for (int e = 0; e < EE; e++) l[e] = 0.f;

    const float* __restrict__ hrow = g_h + (size_t)b * HH;
    for (int k = lane; k < HH; k += 32) {
        const float hv = hrow[k];
        const float4 w0 = *(const float4*)(Rw2 + (size_t)k * EE);
        const float4 w1 = *(const float4*)(Rw2 + (size_t)k * EE + 4);
        l[0] = fmaf(hv, w0.x, l[0]);
        l[1] = fmaf(hv, w0.y, l[1]);
        l[2] = fmaf(hv, w0.z, l[2]);
        l[3] = fmaf(hv, w0.w, l[3]);
        l[4] = fmaf(hv, w1.x, l[4]);
        l[5] = fmaf(hv, w1.y, l[5]);
        l[6] = fmaf(hv, w1.z, l[6]);
        l[7] = fmaf(hv, w1.w, l[7]);
    }
    #pragma unroll
    for (int off = 16; off > 0; off >>= 1)
        #pragma unroll
        for (int e = 0; e < EE; e++)
            l[e] += __shfl_xor_sync(0xffffffff, l[e], off);

    if (lane == 0) {
        #pragma unroll
        for (int e = 0; e < EE; e++) l[e] += Rb2[e];
        int i0 = 0;
        #pragma unroll
        for (int e = 1; e < EE; e++) if (l[e] > l[i0]) i0 = e;
        int i1 = (i0 == 0) ? 1 : 0;
        #pragma unroll
        for (int e = 0; e < EE; e++)
            if (e != i0 && l[e] > l[i1]) i1 = e;
        const float e1 = expf(l[i1] - l[i0]);
        const float inv = 1.f / (1.f + e1);
        g_topk_idx[b * 2 + 0] = i0;
        g_topk_idx[b * 2 + 1] = i1;
        g_topk_a[b * 2 + 0] = inv;
        g_topk_a[b * 2 + 1] = e1 * inv;
        atomicAdd(&g_cnt[i0], 1);
        atomicAdd(&g_cnt[i1], 1);
    }
}

// ---------------- bucket offsets ---------------------------------------------
__global__ void scan_kernel()
{
    if (threadIdx.x == 0) {
        int s = 0;
        for (int e = 0; e < EE; e++) {
            g_off[e] = s;
            g_cursor[e] = s;
            s += g_cnt[e];
        }
    }
}

// ---------------- scatter tokens into expert buckets -------------------------
__global__ __launch_bounds__(256)
void scatter_kernel()
{
    const int b = blockIdx.x * blockDim.x + threadIdx.x;
    if (b >= BB) return;
    #pragma unroll
    for (int j = 0; j < TOPK; j++) {
        const int e = g_topk_idx[b * 2 + j];
        const int pos = atomicAdd(&g_cursor[e], 1);
        g_perm[pos] = b;
        g_wgt[pos]  = g_topk_a[b * 2 + j];
        g_slot[b * 2 + j] = pos;
    }
}

// ---------------- deterministic 2-way combine --------------------------------
__global__ __launch_bounds__(256)
void combine_kernel(float* __restrict__ out)
{
    const int idx = blockIdx.x * blockDim.x + threadIdx.x;
    if (idx >= BB * DD / 4) return;
    const int b = idx / (DD / 4);
    const int q = idx % (DD / 4);
    const int s0 = g_slot[b * 2 + 0];
    const int s1 = g_slot[b * 2 + 1];
    const float4 v0 = *((const float4*)g_eout + (size_t)s0 * (DD / 4) + q);
    const float4 v1 = *((const float4*)g_eout + (size_t)s1 * (DD / 4) + q);
    ((float4*)out)[idx] = make_float4(v0.x + v1.x, v0.y + v1.y, v0.z + v1.z, v0.w + v1.w);
}

// ---------------- launch -----------------------------------------------------
extern "C" void kernel_launch(void* const* d_in, const int* in_sizes, int n_in,
                              void* d_out, int out_size)
{
    const float* t   = (const float*)d_in[0];
    const float* x   = (const float*)d_in[1];
    const float* Rw1 = (const float*)d_in[2];
    const float* Rb1 = (const float*)d_in[3];
    const float* Rw2 = (const float*)d_in[4];
    const float* Rb2 = (const float*)d_in[5];
    const float* Ew1 = (const float*)d_in[6];
    const float* Eb1 = (const float*)d_in[7];
    const float* Ew2 = (const float*)d_in[8];
    const float* Eb2 = (const float*)d_in[9];
    const float* Ew3 = (const float*)d_in[10];
    const float* Eb3 = (const float*)d_in[11];
    float* out = (float*)d_out;

    reset_kernel<<<1, 32>>>();

    // router hidden: exact fp32 (gating selection must match reference)
    router_gemm_kernel<<<dim3(HH / 128, BB / 128, 1), 256>>>(x, t, Rw1, Rb1);

    // logits + top-2 softmax gate (exact fp32)
    logits_topk_kernel<<<BB / 8, 256>>>(Rw2, Rb2);
    scan_kernel<<<1, 32>>>();
    scatter_kernel<<<BB / 256, 256>>>();

    // grouped expert MLP on tensor cores (FP16 mma, fp32 accum)
    // y=256 tiles covers worst-case imbalance (up to 32768 rows in one expert)
    hgemm_kernel<1><<<dim3(HH / 128, 256, EE), 256>>>(x, t, Ew1, Eb1);
    hgemm_kernel<2><<<dim3(HH / 128, 256, EE), 256>>>(nullptr, nullptr, Ew2, Eb2);
    hgemm_kernel<3><<<dim3(DD / 128, 256, EE), 256>>>(nullptr, nullptr, Ew3, Eb3);

    // out[b] = alpha0*eout[slot0] + alpha1*eout[slot1]
    combine_kernel<<<(BB * DD / 4 + 255) / 256, 256>>>(out);
}